// round 13
// baseline (speedup 1.0000x reference)
#include <cuda_runtime.h>

#define B_  2
#define S_  2048
#define D_  1024
#define H_  16
#define DK_ 64
#define DI_ 4096
#define M_  (B_*S_)   // 4096 tokens
#define NROWS_ (32*2048)   // total attention rows

// ---------------- scratch (no allocations allowed) ----------------
__device__ float g_q[M_*D_];
__device__ float g_k[M_*D_];
__device__ float g_v[M_*D_];
__device__ float g_ctx[M_*D_];
__device__ float g_t1[M_*D_];          // doubles as x_tf32 during QKV phase
__device__ float g_ao[M_*D_];
__device__ float g_hid[(size_t)M_*DI_];
__device__ float g_t2[M_*D_];
__device__ float g_wtf[12*1024*1024];  // tf32 weights: wq|wk|wv|fc|w1|w2
__device__ float g_pm[(size_t)NROWS_*16];   // per (row, ktile) partial max
__device__ float g_ps[(size_t)NROWS_*16];   // per (row, ktile) partial expsum

__device__ __forceinline__ float f2tf32(float x) {
    unsigned y;
    asm("cvt.rna.tf32.f32 %0, %1;" : "=r"(y) : "f"(x));
    return __uint_as_float(y);
}

__device__ __forceinline__ void cp16(float* dst, const float* src) {
    unsigned d = (unsigned)__cvta_generic_to_shared(dst);
    asm volatile("cp.async.cg.shared.global [%0], [%1], 16;" :: "r"(d), "l"(src));
}
__device__ __forceinline__ void cp_commit() {
    asm volatile("cp.async.commit_group;" ::: "memory");
}
template<int N> __device__ __forceinline__ void cp_wait() {
    asm volatile("cp.async.wait_group %0;" :: "n"(N) : "memory");
}
// streaming (evict-first) store: probs are written once, never re-read
__device__ __forceinline__ void stcs2(float* p, float a, float b) {
    asm volatile("st.global.cs.v2.f32 [%0], {%1,%2};" :: "l"(p), "f"(a), "f"(b));
}

#define MMA_TF32(d, a, b)                                                      \
    asm volatile(                                                              \
        "mma.sync.aligned.m16n8k8.row.col.f32.tf32.tf32.f32 "                  \
        "{%0,%1,%2,%3}, {%4,%5,%6,%7}, {%8,%9}, {%0,%1,%2,%3};"                \
        : "+f"((d)[0]), "+f"((d)[1]), "+f"((d)[2]), "+f"((d)[3])               \
        : "r"((a)[0]), "r"((a)[1]), "r"((a)[2]), "r"((a)[3]),                  \
          "r"((b)[0]), "r"((b)[1]))

// =================== fused tf32 pre-convert (7 segments, 1 launch) ===================
struct CvtAll { const float* src[7]; float* dst[7]; int n4[7]; };
__global__ void cvt_all_k(CvtAll a) {
    int i = blockIdx.x * blockDim.x + threadIdx.x;
    #pragma unroll
    for (int s = 0; s < 7; s++) {
        int n = a.n4[s];
        if (i < n) {
            float4 v = ((const float4*)a.src[s])[i];
            float4 o = { f2tf32(v.x), f2tf32(v.y), f2tf32(v.z), f2tf32(v.w) };
            ((float4*)a.dst[s])[i] = o;
            return;
        }
        i -= n;
    }
}

// =================== tf32 GEMM, cp.async 3-stage pipelined ===================
struct GemmArgs {
    const float* W[3];
    const float* bias[3];
    float*       C[3];
};

__device__ __forceinline__ void gemm_stage(float* sA, float* sB,
                                           const float* A, const float* W,
                                           int bm, int bn, int Kdim, int k0, int tid) {
    #pragma unroll
    for (int j = 0; j < 4; j++) {
        int idx = tid + j * 256;
        int r = idx >> 3, c4 = idx & 7;
        cp16(&sA[r * 36 + c4 * 4], &A[(size_t)(bm + r) * Kdim + k0 + c4 * 4]);
        cp16(&sB[r * 36 + c4 * 4], &W[(size_t)(bn + r) * Kdim + k0 + c4 * 4]);
    }
    cp_commit();
}

template<bool RELU, bool ACVT>
__global__ __launch_bounds__(256, 2) void tgemm_cp(const float* __restrict__ A,
                                                   GemmArgs args,
                                                   int Ndim, int Kdim) {
    extern __shared__ float smem[];           // 3 * 9216 floats = 110592 B
    const int z = blockIdx.z;
    const float* W    = args.W[z];
    const float* bias = args.bias[z];
    float*       C    = args.C[z];
    const int bm = blockIdx.y * 128;
    const int bn = blockIdx.x * 128;
    const int tid  = threadIdx.x;
    const int lane = tid & 31;
    const int w    = tid >> 5;
    const int wm = (w & 1) * 64;
    const int wn = (w >> 1) * 32;
    const int gid = lane >> 2;
    const int tig = lane & 3;

    float acc[4][4][4] = {};

    const int nst = Kdim / 32;
    gemm_stage(smem, smem + 4608, A, W, bm, bn, Kdim, 0, tid);
    gemm_stage(smem + 9216, smem + 9216 + 4608, A, W, bm, bn, Kdim, 32, tid);
    int pf = 2;
    for (int i = 0; i < nst; i++) {
        if (pf < nst) {
            float* base = smem + (pf % 3) * 9216;
            gemm_stage(base, base + 4608, A, W, bm, bn, Kdim, pf * 32, tid);
            pf++;
            cp_wait<2>();
        } else if (i + 1 < nst) {
            cp_wait<1>();
        } else {
            cp_wait<0>();
        }
        __syncthreads();
        float* sA = smem + (i % 3) * 9216;
        float* sB = sA + 4608;
        #pragma unroll
        for (int k8 = 0; k8 < 4; k8++) {
            const int kb = k8 * 8;
            unsigned af[4][4], bf[4][2];
            #pragma unroll
            for (int mt = 0; mt < 4; mt++) {
                int r = wm + mt * 16 + gid;
                float a0 = sA[(r    ) * 36 + kb + tig];
                float a1 = sA[(r + 8) * 36 + kb + tig];
                float a2 = sA[(r    ) * 36 + kb + tig + 4];
                float a3 = sA[(r + 8) * 36 + kb + tig + 4];
                if (ACVT) { a0 = f2tf32(a0); a1 = f2tf32(a1); a2 = f2tf32(a2); a3 = f2tf32(a3); }
                af[mt][0] = __float_as_uint(a0);
                af[mt][1] = __float_as_uint(a1);
                af[mt][2] = __float_as_uint(a2);
                af[mt][3] = __float_as_uint(a3);
            }
            #pragma unroll
            for (int nt = 0; nt < 4; nt++) {
                int rn = wn + nt * 8 + gid;
                bf[nt][0] = __float_as_uint(sB[rn * 36 + kb + tig]);
                bf[nt][1] = __float_as_uint(sB[rn * 36 + kb + tig + 4]);
            }
            #pragma unroll
            for (int mt = 0; mt < 4; mt++)
                #pragma unroll
                for (int nt = 0; nt < 4; nt++)
                    MMA_TF32(acc[mt][nt], af[mt], bf[nt]);
        }
        __syncthreads();
    }

    #pragma unroll
    for (int nt = 0; nt < 4; nt++) {
        int c = bn + wn + nt * 8 + tig * 2;
        float b0 = bias[c], b1 = bias[c + 1];
        #pragma unroll
        for (int mt = 0; mt < 4; mt++) {
            int r0 = bm + wm + mt * 16 + gid;
            float v0 = acc[mt][nt][0] + b0;
            float v1 = acc[mt][nt][1] + b1;
            float v2 = acc[mt][nt][2] + b0;
            float v3 = acc[mt][nt][3] + b1;
            if (RELU) {
                v0 = fmaxf(v0, 0.0f); v1 = fmaxf(v1, 0.0f);
                v2 = fmaxf(v2, 0.0f); v3 = fmaxf(v3, 0.0f);
            }
            float2 p0 = { v0, v1 }, p1 = { v2, v3 };
            *(float2*)&C[(size_t)r0 * Ndim + c]       = p0;
            *(float2*)&C[(size_t)(r0 + 8) * Ndim + c] = p1;
        }
    }
}

// =================== attention pass 1: softmax partials ONLY (no P stores) ===================
__global__ __launch_bounds__(256, 2) void attn_part(const float* __restrict__ Q,
                                                    const float* __restrict__ K) {
    extern __shared__ float smem[];           // 4 stages * 5120 floats = 81920 B
    const int bh = blockIdx.z;
    const int b = bh >> 4;
    const int h = bh & 15;
    const int bm = blockIdx.y * 128;
    const int bn = blockIdx.x * 128;
    const int tid  = threadIdx.x;
    const int lane = tid & 31;
    const int w    = tid >> 5;
    const int wm = (w & 1) * 64;
    const int wn = (w >> 1) * 32;
    const int gid = lane >> 2;
    const int tig = lane & 3;
    const float* Qb = Q + (size_t)(b * S_ + bm) * D_ + h * 64;
    const float* Kb = K + (size_t)(b * S_ + bn) * D_ + h * 64;

    #pragma unroll
    for (int s = 0; s < 4; s++) {
        float* sQ = smem + s * 5120;
        float* sK = sQ + 2560;
        #pragma unroll
        for (int j = 0; j < 2; j++) {
            int idx = tid + j * 256;
            int r = idx >> 2, c4 = idx & 3;
            cp16(&sQ[r * 20 + c4 * 4], &Qb[(size_t)r * D_ + s * 16 + c4 * 4]);
            cp16(&sK[r * 20 + c4 * 4], &Kb[(size_t)r * D_ + s * 16 + c4 * 4]);
        }
        cp_commit();
    }

    float acc[4][4][4] = {};

    #pragma unroll
    for (int s = 0; s < 4; s++) {
        switch (s) {
            case 0: cp_wait<3>(); break;
            case 1: cp_wait<2>(); break;
            case 2: cp_wait<1>(); break;
            default: cp_wait<0>();
        }
        __syncthreads();
        float* sQ = smem + s * 5120;
        float* sK = sQ + 2560;
        #pragma unroll
        for (int k8 = 0; k8 < 2; k8++) {
            const int kb = k8 * 8;
            unsigned bf[4][2];
            #pragma unroll
            for (int nt = 0; nt < 4; nt++) {
                int rn = wn + nt * 8 + gid;
                bf[nt][0] = __float_as_uint(f2tf32(sK[rn * 20 + kb + tig]));
                bf[nt][1] = __float_as_uint(f2tf32(sK[rn * 20 + kb + tig + 4]));
            }
            float qr[4][4], qh[4][4];
            #pragma unroll
            for (int mt = 0; mt < 4; mt++) {
                int r = wm + mt * 16 + gid;
                qr[mt][0] = sQ[(r    ) * 20 + kb + tig];
                qr[mt][1] = sQ[(r + 8) * 20 + kb + tig];
                qr[mt][2] = sQ[(r    ) * 20 + kb + tig + 4];
                qr[mt][3] = sQ[(r + 8) * 20 + kb + tig + 4];
                qh[mt][0] = f2tf32(qr[mt][0]);
                qh[mt][1] = f2tf32(qr[mt][1]);
                qh[mt][2] = f2tf32(qr[mt][2]);
                qh[mt][3] = f2tf32(qr[mt][3]);
            }
            #pragma unroll
            for (int mt = 0; mt < 4; mt++) {
                unsigned af[4] = { __float_as_uint(qh[mt][0]), __float_as_uint(qh[mt][1]),
                                   __float_as_uint(qh[mt][2]), __float_as_uint(qh[mt][3]) };
                #pragma unroll
                for (int nt = 0; nt < 4; nt++)
                    MMA_TF32(acc[mt][nt], af, bf[nt]);
            }
            #pragma unroll
            for (int mt = 0; mt < 4; mt++) {
                unsigned af[4] = {
                    __float_as_uint(f2tf32(qr[mt][0] - qh[mt][0])),
                    __float_as_uint(f2tf32(qr[mt][1] - qh[mt][1])),
                    __float_as_uint(f2tf32(qr[mt][2] - qh[mt][2])),
                    __float_as_uint(f2tf32(qr[mt][3] - qh[mt][3])) };
                #pragma unroll
                for (int nt = 0; nt < 4; nt++)
                    MMA_TF32(acc[mt][nt], af, bf[nt]);
            }
        }
    }

    // ---- softmax partials over this 128-wide k-tile (identical arithmetic) ----
    const float scale = 0.125f;  // 1/sqrt(64)
    __syncthreads();
    float* sPm = smem;
    float* sPs = smem + 512;
    #pragma unroll
    for (int mt = 0; mt < 4; mt++) {
        #pragma unroll
        for (int hf = 0; hf < 2; hf++) {
            float vv[8];
            #pragma unroll
            for (int nt = 0; nt < 4; nt++) {
                vv[nt * 2]     = acc[mt][nt][hf * 2]     * scale;
                vv[nt * 2 + 1] = acc[mt][nt][hf * 2 + 1] * scale;
            }
            float m = vv[0];
            #pragma unroll
            for (int i2 = 1; i2 < 8; i2++) m = fmaxf(m, vv[i2]);
            float s = 0.0f;
            #pragma unroll
            for (int i2 = 0; i2 < 8; i2++) s += __expf(vv[i2] - m);
            #pragma unroll
            for (int o = 1; o <= 2; o <<= 1) {
                float m2 = __shfl_xor_sync(0xffffffffu, m, o);
                float s2 = __shfl_xor_sync(0xffffffffu, s, o);
                float M2 = fmaxf(m, m2);
                s = s * __expf(m - M2) + s2 * __expf(m2 - M2);
                m = M2;
            }
            if (tig == 0) {
                int rl = wm + mt * 16 + hf * 8 + gid;
                sPm[(w >> 1) * 128 + rl] = m;
                sPs[(w >> 1) * 128 + rl] = s;
            }
        }
    }
    __syncthreads();
    if (tid < 128) {
        float m = sPm[tid];
        float s = sPs[tid];
        #pragma unroll
        for (int t = 1; t < 4; t++) {
            float m2 = sPm[t * 128 + tid], s2 = sPs[t * 128 + tid];
            float M2 = fmaxf(m, m2);
            s = s * __expf(m - M2) + s2 * __expf(m2 - M2);
            m = M2;
        }
        size_t rowG = (size_t)((h * B_ + b) * S_ + bm + tid);
        g_pm[rowG * 16 + blockIdx.x] = m;
        g_ps[rowG * 16 + blockIdx.x] = s;
    }
}

// =================== attention pass 2: recompute QK^T + normalize + write P + P@V ===================
// CTA = (bh, 64-row q-slab). Loops 32 chunks of 64 keys. Q staged once;
// K/V double-buffered. Logit MMA chain identical to pass 1 -> bit-identical probs.
__global__ __launch_bounds__(256, 2) void attn_av2(const float* __restrict__ Q,
                                                   const float* __restrict__ K,
                                                   const float* __restrict__ V,
                                                   float* __restrict__ P,
                                                   float* __restrict__ O) {
    extern __shared__ float smem[];
    // layout (floats): sQ[64*68] @0, sP[64*68] @4352, sM @8704, sI @8768,
    //                  stages @8832: 2 x (sK[64*68] | sV[64*68])
    float* sQ = smem;
    float* sP = smem + 4352;
    float* sM = smem + 8704;
    float* sI = smem + 8768;
    const int bh = blockIdx.z;
    const int b = bh >> 4;
    const int h = bh & 15;
    const int bm = blockIdx.y * 64;
    const int tid  = threadIdx.x;
    const int lane = tid & 31;
    const int w    = tid >> 5;
    const int wm = (w & 1) * 32;
    const int wn = (w >> 1) * 16;
    const int gid = lane >> 2;
    const int tig = lane & 3;
    const float* Qb = Q + (size_t)(b * S_ + bm) * D_ + h * 64;
    const float* Kb = K + (size_t)(b * S_) * D_ + h * 64;
    const float* Vb = V + (size_t)(b * S_) * D_ + h * 64;
    float* Pb = P + ((size_t)(h * B_ + b) * S_ + bm) * S_;
    const float scale = 0.125f;

    // prologue: Q slab + K/V chunk 0 (one group)
    #pragma unroll
    for (int j = 0; j < 4; j++) {
        int idx = tid + j * 256;
        int r = idx >> 4, c4 = idx & 15;
        cp16(&sQ[r * 68 + c4 * 4], &Qb[(size_t)r * D_ + c4 * 4]);
    }
    {
        float* sK = smem + 8832;
        float* sV = sK + 4352;
        #pragma unroll
        for (int j = 0; j < 4; j++) {
            int idx = tid + j * 256;
            int r = idx >> 4, c4 = idx & 15;
            cp16(&sK[r * 68 + c4 * 4], &Kb[(size_t)r * D_ + c4 * 4]);
            cp16(&sV[r * 68 + c4 * 4], &Vb[(size_t)r * D_ + c4 * 4]);
        }
    }
    cp_commit();

    // inline row reduce (identical arithmetic to rowred), overlapped with loads
    if (tid < 64) {
        size_t row = (size_t)((h * B_ + b) * S_ + bm + tid);
        const float* pm = g_pm + row * 16;
        const float* ps = g_ps + row * 16;
        float m = pm[0];
        #pragma unroll
        for (int t = 1; t < 16; t++) m = fmaxf(m, pm[t]);
        float s = 0.0f;
        #pragma unroll
        for (int t = 0; t < 16; t++) s += ps[t] * __expf(pm[t] - m);
        sM[tid] = m;
        sI[tid] = 1.0f / s;
    }

    float accpv[2][2][4] = {};

    const int nck = S_ / 64;   // 32 chunks
    for (int i = 0; i < nck; i++) {
        if (i + 1 < nck) {
            int k0 = (i + 1) * 64;
            float* sK = smem + 8832 + ((i + 1) & 1) * 8704;
            float* sV = sK + 4352;
            #pragma unroll
            for (int j = 0; j < 4; j++) {
                int idx = tid + j * 256;
                int r = idx >> 4, c4 = idx & 15;
                cp16(&sK[r * 68 + c4 * 4], &Kb[(size_t)(k0 + r) * D_ + c4 * 4]);
                cp16(&sV[r * 68 + c4 * 4], &Vb[(size_t)(k0 + r) * D_ + c4 * 4]);
            }
            cp_commit();
            cp_wait<1>();
        } else {
            cp_wait<0>();
        }
        __syncthreads();
        float* sK = smem + 8832 + (i & 1) * 8704;
        float* sV = sK + 4352;

        // ---- recompute QK^T for this 64x64 tile (split-Q, k8 ascending) ----
        float accqk[2][2][4] = {};
        #pragma unroll
        for (int k8 = 0; k8 < 8; k8++) {
            const int kb = k8 * 8;
            unsigned bf[2][2];
            #pragma unroll
            for (int nt = 0; nt < 2; nt++) {
                int rn = wn + nt * 8 + gid;
                bf[nt][0] = __float_as_uint(f2tf32(sK[rn * 68 + kb + tig]));
                bf[nt][1] = __float_as_uint(f2tf32(sK[rn * 68 + kb + tig + 4]));
            }
            float qr[2][4], qh[2][4];
            #pragma unroll
            for (int mt = 0; mt < 2; mt++) {
                int r = wm + mt * 16 + gid;
                qr[mt][0] = sQ[(r    ) * 68 + kb + tig];
                qr[mt][1] = sQ[(r + 8) * 68 + kb + tig];
                qr[mt][2] = sQ[(r    ) * 68 + kb + tig + 4];
                qr[mt][3] = sQ[(r + 8) * 68 + kb + tig + 4];
                qh[mt][0] = f2tf32(qr[mt][0]);
                qh[mt][1] = f2tf32(qr[mt][1]);
                qh[mt][2] = f2tf32(qr[mt][2]);
                qh[mt][3] = f2tf32(qr[mt][3]);
            }
            #pragma unroll
            for (int mt = 0; mt < 2; mt++) {
                unsigned af[4] = { __float_as_uint(qh[mt][0]), __float_as_uint(qh[mt][1]),
                                   __float_as_uint(qh[mt][2]), __float_as_uint(qh[mt][3]) };
                #pragma unroll
                for (int nt = 0; nt < 2; nt++)
                    MMA_TF32(accqk[mt][nt], af, bf[nt]);
            }
            #pragma unroll
            for (int mt = 0; mt < 2; mt++) {
                unsigned af[4] = {
                    __float_as_uint(f2tf32(qr[mt][0] - qh[mt][0])),
                    __float_as_uint(f2tf32(qr[mt][1] - qh[mt][1])),
                    __float_as_uint(f2tf32(qr[mt][2] - qh[mt][2])),
                    __float_as_uint(f2tf32(qr[mt][3] - qh[mt][3])) };
                #pragma unroll
                for (int nt = 0; nt < 2; nt++)
                    MMA_TF32(accqk[mt][nt], af, bf[nt]);
            }
        }

        // ---- normalize, write probs (.cs), stage tile into sP ----
        #pragma unroll
        for (int nt = 0; nt < 2; nt++) {
            int lc = wn + nt * 8 + tig * 2;
            size_t gc = (size_t)i * 64 + lc;
            #pragma unroll
            for (int mt = 0; mt < 2; mt++) {
                int rl = wm + mt * 16 + gid;
                float m0 = sM[rl], i0 = sI[rl];
                float m1 = sM[rl + 8], i1 = sI[rl + 8];
                float p0 = __expf(accqk[mt][nt][0] * scale - m0) * i0;
                float p1 = __expf(accqk[mt][nt][1] * scale - m0) * i0;
                float p2 = __expf(accqk[mt][nt][2] * scale - m1) * i1;
                float p3 = __expf(accqk[mt][nt][3] * scale - m1) * i1;
                stcs2(&Pb[(size_t)rl * S_ + gc], p0, p1);
                stcs2(&Pb[(size_t)(rl + 8) * S_ + gc], p2, p3);
                sP[rl * 68 + lc] = p0;
                sP[rl * 68 + lc + 1] = p1;
                sP[(rl + 8) * 68 + lc] = p2;
                sP[(rl + 8) * 68 + lc + 1] = p3;
            }
        }
        __syncthreads();

        // ---- P @ V for this chunk ----
        #pragma unroll
        for (int k8 = 0; k8 < 8; k8++) {
            const int kb = k8 * 8;
            unsigned af[2][4], bf[2][2];
            #pragma unroll
            for (int mt = 0; mt < 2; mt++) {
                int r = wm + mt * 16 + gid;
                af[mt][0] = __float_as_uint(f2tf32(sP[(r    ) * 68 + kb + tig]));
                af[mt][1] = __float_as_uint(f2tf32(sP[(r + 8) * 68 + kb + tig]));
                af[mt][2] = __float_as_uint(f2tf32(sP[(r    ) * 68 + kb + tig + 4]));
                af[mt][3] = __float_as_uint(f2tf32(sP[(r + 8) * 68 + kb + tig + 4]));
            }
            #pragma unroll
            for (int nt = 0; nt < 2; nt++) {
                int n = wn + nt * 8 + gid;
                bf[nt][0] = __float_as_uint(f2tf32(sV[(kb + tig    ) * 68 + n]));
                bf[nt][1] = __float_as_uint(f2tf32(sV[(kb + tig + 4) * 68 + n]));
            }
            #pragma unroll
            for (int mt = 0; mt < 2; mt++)
                #pragma unroll
                for (int nt = 0; nt < 2; nt++)
                    MMA_TF32(accpv[mt][nt], af[mt], bf[nt]);
        }
        __syncthreads();
    }

    #pragma unroll
    for (int nt = 0; nt < 2; nt++) {
        int c = h * 64 + wn + nt * 8 + tig * 2;
        #pragma unroll
        for (int mt = 0; mt < 2; mt++) {
            int r0 = b * S_ + bm + wm + mt * 16 + gid;
            float2 p0 = { accpv[mt][nt][0], accpv[mt][nt][1] };
            float2 p1 = { accpv[mt][nt][2], accpv[mt][nt][3] };
            *(float2*)&O[(size_t)r0 * D_ + c]       = p0;
            *(float2*)&O[(size_t)(r0 + 8) * D_ + c] = p1;
        }
    }
}

// =================== out = LayerNorm(x + res) * g + b ===================
__global__ __launch_bounds__(256) void add_ln(const float* __restrict__ x,
                                              const float* __restrict__ res,
                                              const float* __restrict__ g,
                                              const float* __restrict__ bta,
                                              float* __restrict__ out) {
    const int row = blockIdx.x;
    const int tid = threadIdx.x;
    const float* xr = x + (size_t)row * D_;
    const float* rr = res + (size_t)row * D_;
    float v[4];
    float s = 0.0f;
    #pragma unroll
    for (int i = 0; i < 4; i++) { v[i] = xr[tid + i * 256] + rr[tid + i * 256]; s += v[i]; }
    __shared__ float red[8];
    #pragma unroll
    for (int o = 16; o > 0; o >>= 1) s += __shfl_xor_sync(0xffffffffu, s, o);
    if ((tid & 31) == 0) red[tid >> 5] = s;
    __syncthreads();
    s = red[0];
    #pragma unroll
    for (int i = 1; i < 8; i++) s += red[i];
    const float mu = s * (1.0f / (float)D_);
    __syncthreads();
    float vs = 0.0f;
    #pragma unroll
    for (int i = 0; i < 4; i++) { float d = v[i] - mu; vs += d * d; }
    #pragma unroll
    for (int o = 16; o > 0; o >>= 1) vs += __shfl_xor_sync(0xffffffffu, vs, o);
    if ((tid & 31) == 0) red[tid >> 5] = vs;
    __syncthreads();
    vs = red[0];
    #pragma unroll
    for (int i = 1; i < 8; i++) vs += red[i];
    const float inv = rsqrtf(vs * (1.0f / (float)D_) + 1e-5f);
    #pragma unroll
    for (int i = 0; i < 4; i++) {
        int col = tid + i * 256;
        out[(size_t)row * D_ + col] = (v[i] - mu) * inv * g[col] + bta[col];
    }
}

// ---------------- launch ----------------
extern "C" void kernel_launch(void* const* d_in, const int* in_sizes, int n_in,
                              void* d_out, int out_size) {
    const float* x     = (const float*)d_in[0];
    const float* wq_w  = (const float*)d_in[1];
    const float* wq_b  = (const float*)d_in[2];
    const float* wk_w  = (const float*)d_in[3];
    const float* wk_b  = (const float*)d_in[4];
    const float* wv_w  = (const float*)d_in[5];
    const float* wv_b  = (const float*)d_in[6];
    const float* fc_w  = (const float*)d_in[7];
    const float* fc_b  = (const float*)d_in[8];
    const float* ln1_g = (const float*)d_in[9];
    const float* ln1_b = (const float*)d_in[10];
    const float* w1_w  = (const float*)d_in[11];
    const float* w1_b  = (const float*)d_in[12];
    const float* w2_w  = (const float*)d_in[13];
    const float* w2_b  = (const float*)d_in[14];
    const float* ln2_g = (const float*)d_in[15];
    const float* ln2_b = (const float*)d_in[16];

    float* out     = (float*)d_out;
    float* enc_out = out;                                   // [2,2048,1024]
    float* attn    = out + (size_t)B_ * S_ * D_;            // [32,2048,2048]

    static float *q = nullptr, *k, *v, *ctx, *t1, *ao, *hid, *t2, *wtf;
    if (!q) {
        cudaGetSymbolAddress((void**)&q,   g_q);
        cudaGetSymbolAddress((void**)&k,   g_k);
        cudaGetSymbolAddress((void**)&v,   g_v);
        cudaGetSymbolAddress((void**)&ctx, g_ctx);
        cudaGetSymbolAddress((void**)&t1,  g_t1);
        cudaGetSymbolAddress((void**)&ao,  g_ao);
        cudaGetSymbolAddress((void**)&hid, g_hid);
        cudaGetSymbolAddress((void**)&t2,  g_t2);
        cudaGetSymbolAddress((void**)&wtf, g_wtf);
        cudaFuncSetAttribute(tgemm_cp<false,false>, cudaFuncAttributeMaxDynamicSharedMemorySize, 110592);
        cudaFuncSetAttribute(tgemm_cp<false,true>,  cudaFuncAttributeMaxDynamicSharedMemorySize, 110592);
        cudaFuncSetAttribute(tgemm_cp<true,true>,   cudaFuncAttributeMaxDynamicSharedMemorySize, 110592);
        cudaFuncSetAttribute(attn_part, cudaFuncAttributeMaxDynamicSharedMemorySize, 81920);
        cudaFuncSetAttribute(attn_av2,  cudaFuncAttributeMaxDynamicSharedMemorySize, 104960);
    }

    float* wq_t = wtf;
    float* wk_t = wtf + (1u << 20);
    float* wv_t = wtf + (2u << 20);
    float* fc_t = wtf + (3u << 20);
    float* w1_t = wtf + (4u << 20);
    float* w2_t = wtf + (8u << 20);
    float* x_t  = t1;   // t1 is free until the fc GEMM

    dim3 blk(256);

    // single fused tf32 pre-convert
    {
        CvtAll a;
        a.src[0] = x;    a.dst[0] = x_t;  a.n4[0] = M_*D_/4;
        a.src[1] = wq_w; a.dst[1] = wq_t; a.n4[1] = D_*D_/4;
        a.src[2] = wk_w; a.dst[2] = wk_t; a.n4[2] = D_*D_/4;
        a.src[3] = wv_w; a.dst[3] = wv_t; a.n4[3] = D_*D_/4;
        a.src[4] = fc_w; a.dst[4] = fc_t; a.n4[4] = D_*D_/4;
        a.src[5] = w1_w; a.dst[5] = w1_t; a.n4[5] = DI_*D_/4;
        a.src[6] = w2_w; a.dst[6] = w2_t; a.n4[6] = DI_*D_/4;
        int total4 = M_*D_/4 + 4*(D_*D_/4) + 2*(DI_*D_/4);
        cvt_all_k<<<(total4 + 255)/256, blk>>>(a);
    }

    // QKV fused (z selects weight)
    {
        GemmArgs a;
        a.W[0] = wq_t; a.W[1] = wk_t; a.W[2] = wv_t;
        a.bias[0] = wq_b; a.bias[1] = wk_b; a.bias[2] = wv_b;
        a.C[0] = q; a.C[1] = k; a.C[2] = v;
        tgemm_cp<false,false><<<dim3(D_/128, M_/128, 3), blk, 110592>>>(x_t, a, D_, D_);
    }

    // attention: partials-only pass -> recompute+normalize+write+PV pass
    attn_part<<<dim3(S_/128, S_/128, B_*H_), blk, 81920>>>(q, k);
    attn_av2<<<dim3(1, S_/64, B_*H_), blk, 104960>>>(q, k, v, attn, ctx);

    // fc + residual + LN1
    {
        GemmArgs a = {};
        a.W[0] = fc_t; a.bias[0] = fc_b; a.C[0] = t1;
        tgemm_cp<false,true><<<dim3(D_/128, M_/128, 1), blk, 110592>>>(ctx, a, D_, D_);
    }
    add_ln<<<M_, blk>>>(t1, x, ln1_g, ln1_b, ao);

    // FFN + residual + LN2
    {
        GemmArgs a = {};
        a.W[0] = w1_t; a.bias[0] = w1_b; a.C[0] = hid;
        tgemm_cp<true,true><<<dim3(DI_/128, M_/128, 1), blk, 110592>>>(ao, a, DI_, D_);
    }
    {
        GemmArgs a = {};
        a.W[0] = w2_t; a.bias[0] = w2_b; a.C[0] = t2;
        tgemm_cp<false,true><<<dim3(D_/128, M_/128, 1), blk, 110592>>>(hid, a, D_, DI_);
    }
    add_ln<<<M_, blk>>>(t2, ao, ln2_g, ln2_b, enc_out);
}

// round 14
// speedup vs baseline: 1.1551x; 1.1551x over previous
#include <cuda_runtime.h>

#define B_  2
#define S_  2048
#define D_  1024
#define H_  16
#define DK_ 64
#define DI_ 4096
#define M_  (B_*S_)   // 4096 tokens
#define NROWS_ (32*2048)   // total attention rows

// ---------------- scratch (no allocations allowed) ----------------
__device__ float g_q[M_*D_];
__device__ float g_k[M_*D_];
__device__ float g_v[M_*D_];
__device__ float g_ctx[M_*D_];
__device__ float g_t1[M_*D_];          // doubles as x_tf32 during QKV phase
__device__ float g_ao[M_*D_];
__device__ float g_hid[(size_t)M_*DI_];
__device__ float g_t2[M_*D_];
__device__ float g_wtf[12*1024*1024];  // tf32 weights: wq|wk|wv|fc|w1|w2
__device__ float g_pm[(size_t)NROWS_*16];   // per (row, ktile) partial max
__device__ float g_ps[(size_t)NROWS_*16];   // per (row, ktile) partial expsum

__device__ __forceinline__ float f2tf32(float x) {
    unsigned y;
    asm("cvt.rna.tf32.f32 %0, %1;" : "=r"(y) : "f"(x));
    return __uint_as_float(y);
}

__device__ __forceinline__ void cp16(float* dst, const float* src) {
    unsigned d = (unsigned)__cvta_generic_to_shared(dst);
    asm volatile("cp.async.cg.shared.global [%0], [%1], 16;" :: "r"(d), "l"(src));
}
__device__ __forceinline__ void cp_commit() {
    asm volatile("cp.async.commit_group;" ::: "memory");
}
template<int N> __device__ __forceinline__ void cp_wait() {
    asm volatile("cp.async.wait_group %0;" :: "n"(N) : "memory");
}
// streaming (evict-first) stores for the huge attention-prob matrix
__device__ __forceinline__ void stcs2(float* p, float2 v) {
    asm volatile("st.global.cs.v2.f32 [%0], {%1,%2};" :: "l"(p), "f"(v.x), "f"(v.y));
}
__device__ __forceinline__ void stcs4(float* p, float4 v) {
    asm volatile("st.global.cs.v4.f32 [%0], {%1,%2,%3,%4};"
                 :: "l"(p), "f"(v.x), "f"(v.y), "f"(v.z), "f"(v.w));
}

#define MMA_TF32(d, a, b)                                                      \
    asm volatile(                                                              \
        "mma.sync.aligned.m16n8k8.row.col.f32.tf32.tf32.f32 "                  \
        "{%0,%1,%2,%3}, {%4,%5,%6,%7}, {%8,%9}, {%0,%1,%2,%3};"                \
        : "+f"((d)[0]), "+f"((d)[1]), "+f"((d)[2]), "+f"((d)[3])               \
        : "r"((a)[0]), "r"((a)[1]), "r"((a)[2]), "r"((a)[3]),                  \
          "r"((b)[0]), "r"((b)[1]))

// =================== fused tf32 pre-convert (7 segments, 1 launch) ===================
struct CvtAll { const float* src[7]; float* dst[7]; int n4[7]; };
__global__ void cvt_all_k(CvtAll a) {
    int i = blockIdx.x * blockDim.x + threadIdx.x;
    #pragma unroll
    for (int s = 0; s < 7; s++) {
        int n = a.n4[s];
        if (i < n) {
            float4 v = ((const float4*)a.src[s])[i];
            float4 o = { f2tf32(v.x), f2tf32(v.y), f2tf32(v.z), f2tf32(v.w) };
            ((float4*)a.dst[s])[i] = o;
            return;
        }
        i -= n;
    }
}

// =================== tf32 GEMM, cp.async 3-stage pipelined ===================
struct GemmArgs {
    const float* W[3];
    const float* bias[3];
    float*       C[3];
};

__device__ __forceinline__ void gemm_stage(float* sA, float* sB,
                                           const float* A, const float* W,
                                           int bm, int bn, int Kdim, int k0, int tid) {
    #pragma unroll
    for (int j = 0; j < 4; j++) {
        int idx = tid + j * 256;
        int r = idx >> 3, c4 = idx & 7;
        cp16(&sA[r * 36 + c4 * 4], &A[(size_t)(bm + r) * Kdim + k0 + c4 * 4]);
        cp16(&sB[r * 36 + c4 * 4], &W[(size_t)(bn + r) * Kdim + k0 + c4 * 4]);
    }
    cp_commit();
}

template<bool RELU, bool ACVT>
__global__ __launch_bounds__(256, 2) void tgemm_cp(const float* __restrict__ A,
                                                   GemmArgs args,
                                                   int Ndim, int Kdim) {
    extern __shared__ float smem[];           // 3 * 9216 floats = 110592 B
    const int z = blockIdx.z;
    const float* W    = args.W[z];
    const float* bias = args.bias[z];
    float*       C    = args.C[z];
    const int bm = blockIdx.y * 128;
    const int bn = blockIdx.x * 128;
    const int tid  = threadIdx.x;
    const int lane = tid & 31;
    const int w    = tid >> 5;
    const int wm = (w & 1) * 64;
    const int wn = (w >> 1) * 32;
    const int gid = lane >> 2;
    const int tig = lane & 3;

    float acc[4][4][4] = {};

    const int nst = Kdim / 32;
    gemm_stage(smem, smem + 4608, A, W, bm, bn, Kdim, 0, tid);
    gemm_stage(smem + 9216, smem + 9216 + 4608, A, W, bm, bn, Kdim, 32, tid);
    int pf = 2;
    for (int i = 0; i < nst; i++) {
        if (pf < nst) {
            float* base = smem + (pf % 3) * 9216;
            gemm_stage(base, base + 4608, A, W, bm, bn, Kdim, pf * 32, tid);
            pf++;
            cp_wait<2>();
        } else if (i + 1 < nst) {
            cp_wait<1>();
        } else {
            cp_wait<0>();
        }
        __syncthreads();
        float* sA = smem + (i % 3) * 9216;
        float* sB = sA + 4608;
        #pragma unroll
        for (int k8 = 0; k8 < 4; k8++) {
            const int kb = k8 * 8;
            unsigned af[4][4], bf[4][2];
            #pragma unroll
            for (int mt = 0; mt < 4; mt++) {
                int r = wm + mt * 16 + gid;
                float a0 = sA[(r    ) * 36 + kb + tig];
                float a1 = sA[(r + 8) * 36 + kb + tig];
                float a2 = sA[(r    ) * 36 + kb + tig + 4];
                float a3 = sA[(r + 8) * 36 + kb + tig + 4];
                if (ACVT) { a0 = f2tf32(a0); a1 = f2tf32(a1); a2 = f2tf32(a2); a3 = f2tf32(a3); }
                af[mt][0] = __float_as_uint(a0);
                af[mt][1] = __float_as_uint(a1);
                af[mt][2] = __float_as_uint(a2);
                af[mt][3] = __float_as_uint(a3);
            }
            #pragma unroll
            for (int nt = 0; nt < 4; nt++) {
                int rn = wn + nt * 8 + gid;
                bf[nt][0] = __float_as_uint(sB[rn * 36 + kb + tig]);
                bf[nt][1] = __float_as_uint(sB[rn * 36 + kb + tig + 4]);
            }
            #pragma unroll
            for (int mt = 0; mt < 4; mt++)
                #pragma unroll
                for (int nt = 0; nt < 4; nt++)
                    MMA_TF32(acc[mt][nt], af[mt], bf[nt]);
        }
        __syncthreads();
    }

    #pragma unroll
    for (int nt = 0; nt < 4; nt++) {
        int c = bn + wn + nt * 8 + tig * 2;
        float b0 = bias[c], b1 = bias[c + 1];
        #pragma unroll
        for (int mt = 0; mt < 4; mt++) {
            int r0 = bm + wm + mt * 16 + gid;
            float v0 = acc[mt][nt][0] + b0;
            float v1 = acc[mt][nt][1] + b1;
            float v2 = acc[mt][nt][2] + b0;
            float v3 = acc[mt][nt][3] + b1;
            if (RELU) {
                v0 = fmaxf(v0, 0.0f); v1 = fmaxf(v1, 0.0f);
                v2 = fmaxf(v2, 0.0f); v3 = fmaxf(v3, 0.0f);
            }
            float2 p0 = { v0, v1 }, p1 = { v2, v3 };
            *(float2*)&C[(size_t)r0 * Ndim + c]       = p0;
            *(float2*)&C[(size_t)(r0 + 8) * Ndim + c] = p1;
        }
    }
}

// =================== attention scores + softmax partials ===================
__global__ __launch_bounds__(256, 2) void attn_scores_tc(const float* __restrict__ Q,
                                                         const float* __restrict__ K,
                                                         float* __restrict__ P) {
    extern __shared__ float smem[];           // 4 stages * 5120 floats = 81920 B
    const int bh = blockIdx.z;
    const int b = bh >> 4;
    const int h = bh & 15;
    const int bm = blockIdx.y * 128;
    const int bn = blockIdx.x * 128;
    const int tid  = threadIdx.x;
    const int lane = tid & 31;
    const int w    = tid >> 5;
    const int wm = (w & 1) * 64;
    const int wn = (w >> 1) * 32;
    const int gid = lane >> 2;
    const int tig = lane & 3;
    const float* Qb = Q + (size_t)(b * S_ + bm) * D_ + h * 64;
    const float* Kb = K + (size_t)(b * S_ + bn) * D_ + h * 64;

    #pragma unroll
    for (int s = 0; s < 4; s++) {
        float* sQ = smem + s * 5120;
        float* sK = sQ + 2560;
        #pragma unroll
        for (int j = 0; j < 2; j++) {
            int idx = tid + j * 256;
            int r = idx >> 2, c4 = idx & 3;
            cp16(&sQ[r * 20 + c4 * 4], &Qb[(size_t)r * D_ + s * 16 + c4 * 4]);
            cp16(&sK[r * 20 + c4 * 4], &Kb[(size_t)r * D_ + s * 16 + c4 * 4]);
        }
        cp_commit();
    }

    float acc[4][4][4] = {};

    #pragma unroll
    for (int s = 0; s < 4; s++) {
        switch (s) {
            case 0: cp_wait<3>(); break;
            case 1: cp_wait<2>(); break;
            case 2: cp_wait<1>(); break;
            default: cp_wait<0>();
        }
        __syncthreads();
        float* sQ = smem + s * 5120;
        float* sK = sQ + 2560;
        #pragma unroll
        for (int k8 = 0; k8 < 2; k8++) {
            const int kb = k8 * 8;
            unsigned bf[4][2];
            #pragma unroll
            for (int nt = 0; nt < 4; nt++) {
                int rn = wn + nt * 8 + gid;
                bf[nt][0] = __float_as_uint(f2tf32(sK[rn * 20 + kb + tig]));
                bf[nt][1] = __float_as_uint(f2tf32(sK[rn * 20 + kb + tig + 4]));
            }
            float qr[4][4], qh[4][4];
            #pragma unroll
            for (int mt = 0; mt < 4; mt++) {
                int r = wm + mt * 16 + gid;
                qr[mt][0] = sQ[(r    ) * 20 + kb + tig];
                qr[mt][1] = sQ[(r + 8) * 20 + kb + tig];
                qr[mt][2] = sQ[(r    ) * 20 + kb + tig + 4];
                qr[mt][3] = sQ[(r + 8) * 20 + kb + tig + 4];
                qh[mt][0] = f2tf32(qr[mt][0]);
                qh[mt][1] = f2tf32(qr[mt][1]);
                qh[mt][2] = f2tf32(qr[mt][2]);
                qh[mt][3] = f2tf32(qr[mt][3]);
            }
            #pragma unroll
            for (int mt = 0; mt < 4; mt++) {
                unsigned af[4] = { __float_as_uint(qh[mt][0]), __float_as_uint(qh[mt][1]),
                                   __float_as_uint(qh[mt][2]), __float_as_uint(qh[mt][3]) };
                #pragma unroll
                for (int nt = 0; nt < 4; nt++)
                    MMA_TF32(acc[mt][nt], af, bf[nt]);
            }
            #pragma unroll
            for (int mt = 0; mt < 4; mt++) {
                unsigned af[4] = {
                    __float_as_uint(f2tf32(qr[mt][0] - qh[mt][0])),
                    __float_as_uint(f2tf32(qr[mt][1] - qh[mt][1])),
                    __float_as_uint(f2tf32(qr[mt][2] - qh[mt][2])),
                    __float_as_uint(f2tf32(qr[mt][3] - qh[mt][3])) };
                #pragma unroll
                for (int nt = 0; nt < 4; nt++)
                    MMA_TF32(acc[mt][nt], af, bf[nt]);
            }
        }
    }

    const float scale = 0.125f;  // 1/sqrt(64)
    #pragma unroll
    for (int nt = 0; nt < 4; nt++) {
        int c = bn + wn + nt * 8 + tig * 2;
        #pragma unroll
        for (int mt = 0; mt < 4; mt++) {
            size_t r0 = (size_t)((h * B_ + b) * S_ + bm + wm + mt * 16 + gid);
            float2 p0 = { acc[mt][nt][0] * scale, acc[mt][nt][1] * scale };
            float2 p1 = { acc[mt][nt][2] * scale, acc[mt][nt][3] * scale };
            stcs2(&P[r0 * S_ + c], p0);
            stcs2(&P[(r0 + 8) * S_ + c], p1);
        }
    }

    // ---- softmax partials over this 128-wide k-tile ----
    __syncthreads();                 // smem tiles fully consumed; reuse
    float* sPm = smem;               // [4][128]
    float* sPs = smem + 512;
    #pragma unroll
    for (int mt = 0; mt < 4; mt++) {
        #pragma unroll
        for (int hf = 0; hf < 2; hf++) {
            float vv[8];
            #pragma unroll
            for (int nt = 0; nt < 4; nt++) {
                vv[nt * 2]     = acc[mt][nt][hf * 2]     * scale;
                vv[nt * 2 + 1] = acc[mt][nt][hf * 2 + 1] * scale;
            }
            float m = vv[0];
            #pragma unroll
            for (int i2 = 1; i2 < 8; i2++) m = fmaxf(m, vv[i2]);
            float s = 0.0f;
            #pragma unroll
            for (int i2 = 0; i2 < 8; i2++) s += __expf(vv[i2] - m);
            #pragma unroll
            for (int o = 1; o <= 2; o <<= 1) {
                float m2 = __shfl_xor_sync(0xffffffffu, m, o);
                float s2 = __shfl_xor_sync(0xffffffffu, s, o);
                float M2 = fmaxf(m, m2);
                s = s * __expf(m - M2) + s2 * __expf(m2 - M2);
                m = M2;
            }
            if (tig == 0) {
                int rl = wm + mt * 16 + hf * 8 + gid;
                sPm[(w >> 1) * 128 + rl] = m;
                sPs[(w >> 1) * 128 + rl] = s;
            }
        }
    }
    __syncthreads();
    if (tid < 128) {
        float m = sPm[tid];
        float s = sPs[tid];
        #pragma unroll
        for (int t = 1; t < 4; t++) {
            float m2 = sPm[t * 128 + tid], s2 = sPs[t * 128 + tid];
            float M2 = fmaxf(m, m2);
            s = s * __expf(m - M2) + s2 * __expf(m2 - M2);
            m = M2;
        }
        size_t rowG = (size_t)((h * B_ + b) * S_ + bm + tid);
        g_pm[rowG * 16 + blockIdx.x] = m;
        g_ps[rowG * 16 + blockIdx.x] = s;
    }
}

// =================== fused rowred + normalize + write-P + P@V, 4-stage ===================
__global__ __launch_bounds__(256, 2) void attn_av_tc(float* __restrict__ P,
                                                     const float* __restrict__ V,
                                                     float* __restrict__ O) {
    extern __shared__ float smem[];           // 4*6784 + 256 floats = 109568 B
    const int bh = blockIdx.z;
    const int b = bh >> 4;
    const int h = bh & 15;
    const int bm = blockIdx.y * 128;
    const int tid  = threadIdx.x;
    const int lane = tid & 31;
    const int w    = tid >> 5;
    const int wm = (w & 1) * 64;
    const int wn = (w >> 1) * 16;
    const int gid = lane >> 2;
    const int tig = lane & 3;
    float* Pb = P + (size_t)(h * B_ + b) * S_ * S_ + (size_t)bm * S_;
    const float* Vb = V + (size_t)(b * S_) * D_ + h * 64;
    float* sM = smem + 27136;
    float* sI = smem + 27264;

    float acc[4][2][4] = {};

    // prologue: stages 0, 1, 2
    #pragma unroll
    for (int s = 0; s < 3; s++) {
        float* sP = smem + s * 6784;
        float* sV = sP + 4608;
        int k0 = s * 32;
        #pragma unroll
        for (int j = 0; j < 4; j++) {
            int idx = tid + j * 256;
            int r = idx >> 3, c4 = idx & 7;
            cp16(&sP[r * 36 + c4 * 4], &Pb[(size_t)r * S_ + k0 + c4 * 4]);
        }
        #pragma unroll
        for (int j = 0; j < 2; j++) {
            int idx = tid + j * 256;
            int r = idx >> 4, c4 = idx & 15;
            cp16(&sV[r * 68 + c4 * 4], &Vb[(size_t)(k0 + r) * D_ + c4 * 4]);
        }
        cp_commit();
    }

    // inline row reduce (identical arithmetic to rowred), overlapped with loads
    if (tid < 128) {
        size_t row = (size_t)((h * B_ + b) * S_ + bm + tid);
        const float* pm = g_pm + row * 16;
        const float* ps = g_ps + row * 16;
        float m = pm[0];
        #pragma unroll
        for (int t = 1; t < 16; t++) m = fmaxf(m, pm[t]);
        float s = 0.0f;
        #pragma unroll
        for (int t = 0; t < 16; t++) s += ps[t] * __expf(pm[t] - m);
        sM[tid] = m;
        sI[tid] = 1.0f / s;
    }

    const int nst = S_ / 32;
    int pf = 3;
    for (int i = 0; i < nst; i++) {
        if (pf < nst) {
            int k0 = pf * 32;
            float* sP = smem + (pf & 3) * 6784;
            float* sV = sP + 4608;
            #pragma unroll
            for (int j = 0; j < 4; j++) {
                int idx = tid + j * 256;
                int r = idx >> 3, c4 = idx & 7;
                cp16(&sP[r * 36 + c4 * 4], &Pb[(size_t)r * S_ + k0 + c4 * 4]);
            }
            #pragma unroll
            for (int j = 0; j < 2; j++) {
                int idx = tid + j * 256;
                int r = idx >> 4, c4 = idx & 15;
                cp16(&sV[r * 68 + c4 * 4], &Vb[(size_t)(k0 + r) * D_ + c4 * 4]);
            }
            cp_commit();
            pf++;
            cp_wait<3>();
        } else if (i + 2 < nst) {
            cp_wait<2>();
        } else if (i + 1 < nst) {
            cp_wait<1>();
        } else {
            cp_wait<0>();
        }
        __syncthreads();
        float* sP = smem + (i & 3) * 6784;
        float* sV = sP + 4608;

        // normalize tile in smem and stream final probs to gmem
        const int k0c = i * 32;
        #pragma unroll
        for (int j = 0; j < 4; j++) {
            int idx = tid + j * 256;
            int r = idx >> 3, c4 = idx & 7;
            float4 vv = *(float4*)&sP[r * 36 + c4 * 4];
            float m = sM[r], ii = sI[r];
            vv.x = __expf(vv.x - m) * ii;
            vv.y = __expf(vv.y - m) * ii;
            vv.z = __expf(vv.z - m) * ii;
            vv.w = __expf(vv.w - m) * ii;
            *(float4*)&sP[r * 36 + c4 * 4] = vv;
            stcs4(&Pb[(size_t)r * S_ + k0c + c4 * 4], vv);
        }
        __syncthreads();

        #pragma unroll
        for (int k8 = 0; k8 < 4; k8++) {
            const int kb = k8 * 8;
            unsigned af[4][4], bf[2][2];
            #pragma unroll
            for (int mt = 0; mt < 4; mt++) {
                int r = wm + mt * 16 + gid;
                af[mt][0] = __float_as_uint(f2tf32(sP[(r    ) * 36 + kb + tig]));
                af[mt][1] = __float_as_uint(f2tf32(sP[(r + 8) * 36 + kb + tig]));
                af[mt][2] = __float_as_uint(f2tf32(sP[(r    ) * 36 + kb + tig + 4]));
                af[mt][3] = __float_as_uint(f2tf32(sP[(r + 8) * 36 + kb + tig + 4]));
            }
            #pragma unroll
            for (int nt = 0; nt < 2; nt++) {
                int n = wn + nt * 8 + gid;
                bf[nt][0] = __float_as_uint(f2tf32(sV[(kb + tig    ) * 68 + n]));
                bf[nt][1] = __float_as_uint(f2tf32(sV[(kb + tig + 4) * 68 + n]));
            }
            #pragma unroll
            for (int mt = 0; mt < 4; mt++)
                #pragma unroll
                for (int nt = 0; nt < 2; nt++)
                    MMA_TF32(acc[mt][nt], af[mt], bf[nt]);
        }
        __syncthreads();
    }

    #pragma unroll
    for (int nt = 0; nt < 2; nt++) {
        int c = h * 64 + wn + nt * 8 + tig * 2;
        #pragma unroll
        for (int mt = 0; mt < 4; mt++) {
            int r0 = b * S_ + bm + wm + mt * 16 + gid;
            float2 p0 = { acc[mt][nt][0], acc[mt][nt][1] };
            float2 p1 = { acc[mt][nt][2], acc[mt][nt][3] };
            *(float2*)&O[(size_t)r0 * D_ + c]       = p0;
            *(float2*)&O[(size_t)(r0 + 8) * D_ + c] = p1;
        }
    }
}

// =================== out = LayerNorm(x + res) * g + b ===================
__global__ __launch_bounds__(256) void add_ln(const float* __restrict__ x,
                                              const float* __restrict__ res,
                                              const float* __restrict__ g,
                                              const float* __restrict__ bta,
                                              float* __restrict__ out) {
    const int row = blockIdx.x;
    const int tid = threadIdx.x;
    const float* xr = x + (size_t)row * D_;
    const float* rr = res + (size_t)row * D_;
    float v[4];
    float s = 0.0f;
    #pragma unroll
    for (int i = 0; i < 4; i++) { v[i] = xr[tid + i * 256] + rr[tid + i * 256]; s += v[i]; }
    __shared__ float red[8];
    #pragma unroll
    for (int o = 16; o > 0; o >>= 1) s += __shfl_xor_sync(0xffffffffu, s, o);
    if ((tid & 31) == 0) red[tid >> 5] = s;
    __syncthreads();
    s = red[0];
    #pragma unroll
    for (int i = 1; i < 8; i++) s += red[i];
    const float mu = s * (1.0f / (float)D_);
    __syncthreads();
    float vs = 0.0f;
    #pragma unroll
    for (int i = 0; i < 4; i++) { float d = v[i] - mu; vs += d * d; }
    #pragma unroll
    for (int o = 16; o > 0; o >>= 1) vs += __shfl_xor_sync(0xffffffffu, vs, o);
    if ((tid & 31) == 0) red[tid >> 5] = vs;
    __syncthreads();
    vs = red[0];
    #pragma unroll
    for (int i = 1; i < 8; i++) vs += red[i];
    const float inv = rsqrtf(vs * (1.0f / (float)D_) + 1e-5f);
    #pragma unroll
    for (int i = 0; i < 4; i++) {
        int col = tid + i * 256;
        out[(size_t)row * D_ + col] = (v[i] - mu) * inv * g[col] + bta[col];
    }
}

// ---------------- launch ----------------
extern "C" void kernel_launch(void* const* d_in, const int* in_sizes, int n_in,
                              void* d_out, int out_size) {
    const float* x     = (const float*)d_in[0];
    const float* wq_w  = (const float*)d_in[1];
    const float* wq_b  = (const float*)d_in[2];
    const float* wk_w  = (const float*)d_in[3];
    const float* wk_b  = (const float*)d_in[4];
    const float* wv_w  = (const float*)d_in[5];
    const float* wv_b  = (const float*)d_in[6];
    const float* fc_w  = (const float*)d_in[7];
    const float* fc_b  = (const float*)d_in[8];
    const float* ln1_g = (const float*)d_in[9];
    const float* ln1_b = (const float*)d_in[10];
    const float* w1_w  = (const float*)d_in[11];
    const float* w1_b  = (const float*)d_in[12];
    const float* w2_w  = (const float*)d_in[13];
    const float* w2_b  = (const float*)d_in[14];
    const float* ln2_g = (const float*)d_in[15];
    const float* ln2_b = (const float*)d_in[16];

    float* out     = (float*)d_out;
    float* enc_out = out;                                   // [2,2048,1024]
    float* attn    = out + (size_t)B_ * S_ * D_;            // [32,2048,2048]

    static float *q = nullptr, *k, *v, *ctx, *t1, *ao, *hid, *t2, *wtf;
    if (!q) {
        cudaGetSymbolAddress((void**)&q,   g_q);
        cudaGetSymbolAddress((void**)&k,   g_k);
        cudaGetSymbolAddress((void**)&v,   g_v);
        cudaGetSymbolAddress((void**)&ctx, g_ctx);
        cudaGetSymbolAddress((void**)&t1,  g_t1);
        cudaGetSymbolAddress((void**)&ao,  g_ao);
        cudaGetSymbolAddress((void**)&hid, g_hid);
        cudaGetSymbolAddress((void**)&t2,  g_t2);
        cudaGetSymbolAddress((void**)&wtf, g_wtf);
        cudaFuncSetAttribute(tgemm_cp<false,false>, cudaFuncAttributeMaxDynamicSharedMemorySize, 110592);
        cudaFuncSetAttribute(tgemm_cp<false,true>,  cudaFuncAttributeMaxDynamicSharedMemorySize, 110592);
        cudaFuncSetAttribute(tgemm_cp<true,true>,   cudaFuncAttributeMaxDynamicSharedMemorySize, 110592);
        cudaFuncSetAttribute(attn_scores_tc, cudaFuncAttributeMaxDynamicSharedMemorySize, 81920);
        cudaFuncSetAttribute(attn_av_tc,     cudaFuncAttributeMaxDynamicSharedMemorySize, 109568);
    }

    float* wq_t = wtf;
    float* wk_t = wtf + (1u << 20);
    float* wv_t = wtf + (2u << 20);
    float* fc_t = wtf + (3u << 20);
    float* w1_t = wtf + (4u << 20);
    float* w2_t = wtf + (8u << 20);
    float* x_t  = t1;   // t1 is free until the fc GEMM

    dim3 blk(256);

    // single fused tf32 pre-convert
    {
        CvtAll a;
        a.src[0] = x;    a.dst[0] = x_t;  a.n4[0] = M_*D_/4;
        a.src[1] = wq_w; a.dst[1] = wq_t; a.n4[1] = D_*D_/4;
        a.src[2] = wk_w; a.dst[2] = wk_t; a.n4[2] = D_*D_/4;
        a.src[3] = wv_w; a.dst[3] = wv_t; a.n4[3] = D_*D_/4;
        a.src[4] = fc_w; a.dst[4] = fc_t; a.n4[4] = D_*D_/4;
        a.src[5] = w1_w; a.dst[5] = w1_t; a.n4[5] = DI_*D_/4;
        a.src[6] = w2_w; a.dst[6] = w2_t; a.n4[6] = DI_*D_/4;
        int total4 = M_*D_/4 + 4*(D_*D_/4) + 2*(DI_*D_/4);
        cvt_all_k<<<(total4 + 255)/256, blk>>>(a);
    }

    // QKV fused (z selects weight)
    {
        GemmArgs a;
        a.W[0] = wq_t; a.W[1] = wk_t; a.W[2] = wv_t;
        a.bias[0] = wq_b; a.bias[1] = wk_b; a.bias[2] = wv_b;
        a.C[0] = q; a.C[1] = k; a.C[2] = v;
        tgemm_cp<false,false><<<dim3(D_/128, M_/128, 3), blk, 110592>>>(x_t, a, D_, D_);
    }

    // attention: scores+partials -> fused rowred+normalize+write+PV
    attn_scores_tc<<<dim3(S_/128, S_/128, B_*H_), blk, 81920>>>(q, k, attn);
    attn_av_tc<<<dim3(1, S_/128, B_*H_), blk, 109568>>>(attn, v, ctx);

    // fc + residual + LN1
    {
        GemmArgs a = {};
        a.W[0] = fc_t; a.bias[0] = fc_b; a.C[0] = t1;
        tgemm_cp<false,true><<<dim3(D_/128, M_/128, 1), blk, 110592>>>(ctx, a, D_, D_);
    }
    add_ln<<<M_, blk>>>(t1, x, ln1_g, ln1_b, ao);

    // FFN + residual + LN2
    {
        GemmArgs a = {};
        a.W[0] = w1_t; a.bias[0] = w1_b; a.C[0] = hid;
        tgemm_cp<true,true><<<dim3(DI_/128, M_/128, 1), blk, 110592>>>(ao, a, DI_, D_);
    }
    {
        GemmArgs a = {};
        a.W[0] = w2_t; a.bias[0] = w2_b; a.C[0] = t2;
        tgemm_cp<false,true><<<dim3(D_/128, M_/128, 1), blk, 110592>>>(hid, a, D_, DI_);
    }
    add_ln<<<M_, blk>>>(t2, ao, ln2_g, ln2_b, enc_out);
}